// round 6
// baseline (speedup 1.0000x reference)
#include <cuda_runtime.h>

#define Nn 64
#define Cc 64
#define Tt 300
#define Vv 25
#define Ssub 3
#define TV 7500
#define TB 4                 // t per y-block

// -------- scratch (device globals: no allocation allowed) --------
__device__ float g_ab[(size_t)Nn * 96 * TV];      // [n][96 rows: 0-47 = a, 48-95 = b][t*25+v]
__device__ float g_scores[Nn * Ssub * 625];       // partial score sums
__device__ float g_adapt[Nn * Ssub * 625];        // [n][s][v][w]
__device__ float g_y[(size_t)Nn * Cc * TV];       // [n][o][t*25+w]
__device__ float g_bn[256];                       // sum | sumsq | scale | shift

// -------- kernel 0: zero BN accumulators + score partials --------
__global__ void zero_kernel() {
    unsigned idx = blockIdx.x * 256u + threadIdx.x;
    if (idx < Nn * Ssub * 625) g_scores[idx] = 0.f;
    if (blockIdx.x == 0 && threadIdx.x < 128) g_bn[threadIdx.x] = 0.f;
}

// -------- kernel 1: AB[n] = [wa;wb][96,64] x x[n][64,7500]  (+bias) --------
__global__ void __launch_bounds__(256) proj_kernel(
    const float* __restrict__ x,
    const float* __restrict__ wa, const float* __restrict__ ba,
    const float* __restrict__ wb, const float* __restrict__ bb)
{
    extern __shared__ float sm[];
    float* Ws   = sm;               // 96*65
    float* Bs   = Ws + 96 * 65;     // 64*128
    float* biasS = Bs + 64 * 128;   // 96

    const int n = blockIdx.y;
    const int col0 = blockIdx.x * 128;
    const int tid = threadIdx.x;

    for (int i = tid; i < 96 * 64; i += 256) {
        int r = i >> 6, c = i & 63;
        Ws[r * 65 + c] = (r < 48) ? wa[r * 64 + c] : wb[(r - 48) * 64 + c];
    }
    if (tid < 96) biasS[tid] = (tid < 48) ? ba[tid] : bb[tid - 48];
    for (int i = tid; i < 64 * 128; i += 256) {
        int c = i >> 7, j = i & 127;
        int col = col0 + j;
        Bs[i] = (col < TV) ? x[((size_t)n * Cc + c) * TV + col] : 0.f;
    }
    __syncthreads();

    const int ty = tid >> 4, tx = tid & 15;
    float acc[6][8];
#pragma unroll
    for (int a = 0; a < 6; a++)
#pragma unroll
        for (int b = 0; b < 8; b++) acc[a][b] = 0.f;

    for (int c = 0; c < 64; c++) {
        float wr[6], xr[8];
#pragma unroll
        for (int jm = 0; jm < 6; jm++) wr[jm] = Ws[(ty * 6 + jm) * 65 + c];
#pragma unroll
        for (int jc = 0; jc < 8; jc++) xr[jc] = Bs[c * 128 + tx + 16 * jc];
#pragma unroll
        for (int jm = 0; jm < 6; jm++)
#pragma unroll
            for (int jc = 0; jc < 8; jc++) acc[jm][jc] += wr[jm] * xr[jc];
    }

#pragma unroll
    for (int jm = 0; jm < 6; jm++) {
        int r = ty * 6 + jm;
        size_t base = ((size_t)n * 96 + r) * TV;
        float bias = biasS[r];
#pragma unroll
        for (int jc = 0; jc < 8; jc++) {
            int col = col0 + tx + 16 * jc;
            if (col < TV) g_ab[base + col] = acc[jm][jc] + bias;
        }
    }
}

// -------- kernel 2a: partial scores, split-K over 4 chunks --------
// grid (3, 64, 4), block 256
__global__ void __launch_bounds__(256) scores_part_kernel()
{
    __shared__ float aS[1000];
    __shared__ float bS[1000];
    __shared__ float scS[625];

    const int s = blockIdx.x, n = blockIdx.y, ch = blockIdx.z;
    const int tid = threadIdx.x;

    for (int i = tid; i < 625; i += 256) scS[i] = 0.f;

    const size_t abase = ((size_t)n * 96 + s * 16) * TV;
    const size_t bbase = ((size_t)n * 96 + 48 + s * 16) * TV;

    const int ks = tid / 25;
    const int rem = tid % 25;
    const int wg = rem / 5, vg = rem % 5;

    float acc[5][5];
#pragma unroll
    for (int a = 0; a < 5; a++)
#pragma unroll
        for (int b = 0; b < 5; b++) acc[a][b] = 0.f;

    float4* aS4 = reinterpret_cast<float4*>(aS);
    float4* bS4 = reinterpret_cast<float4*>(bS);

    for (int st = ch * 30; st < ch * 30 + 30; st++) {   // 4 chunks of 30 (×40 k-rows)
        __syncthreads();
        if (tid < 250) {
            const float4* ga = reinterpret_cast<const float4*>(g_ab + abase + (size_t)st * 1000);
            const float4* gb = reinterpret_cast<const float4*>(g_ab + bbase + (size_t)st * 1000);
            aS4[tid] = ga[tid];
            bS4[tid] = gb[tid];
        }
        __syncthreads();
        if (ks < 10) {
#pragma unroll
            for (int j = 0; j < 4; j++) {
                int k = ks * 4 + j;
                float ra[5], rb[5];
#pragma unroll
                for (int iv = 0; iv < 5; iv++) ra[iv] = aS[k * 25 + vg * 5 + iv];
#pragma unroll
                for (int iw = 0; iw < 5; iw++) rb[iw] = bS[k * 25 + wg * 5 + iw];
#pragma unroll
                for (int iv = 0; iv < 5; iv++)
#pragma unroll
                    for (int iw = 0; iw < 5; iw++) acc[iv][iw] += ra[iv] * rb[iw];
            }
        }
    }
    __syncthreads();
    if (ks < 10) {
#pragma unroll
        for (int iv = 0; iv < 5; iv++)
#pragma unroll
            for (int iw = 0; iw < 5; iw++)
                atomicAdd(&scS[(vg * 5 + iv) * 25 + (wg * 5 + iw)], acc[iv][iw]);
    }
    __syncthreads();
    for (int i = tid; i < 625; i += 256)
        atomicAdd(&g_scores[(size_t)(n * 3 + s) * 625 + i], scS[i]);
}

// -------- kernel 2b: softmax(axis=v) + adapt = A+W+attn --------
// grid 192, block 32
__global__ void softmax_adapt_kernel(const float* __restrict__ A, const float* __restrict__ W)
{
    const int b = blockIdx.x;            // n*3+s
    const int s = b % 3;
    const int w = threadIdx.x;
    if (w >= 25) return;
    const float* sc = g_scores + (size_t)b * 625;
    const float inv = 1.f / 4800.f;
    float col[25];
    float m = -1e30f;
#pragma unroll
    for (int v = 0; v < 25; v++) { col[v] = sc[v * 25 + w] * inv; m = fmaxf(m, col[v]); }
    float sum = 0.f;
#pragma unroll
    for (int v = 0; v < 25; v++) { col[v] = expf(col[v] - m); sum += col[v]; }
    float rs = 1.f / sum;
#pragma unroll
    for (int v = 0; v < 25; v++) {
        int widx = (s * 25 + v) * 25 + w;
        g_adapt[(size_t)b * 625 + v * 25 + w] = A[widx] + W[widx] + col[v] * rs;
    }
}

// -------- kernel 3: fused y = sum_s wd[s]^T (x . adapt[s]) + bd, BN partial sums --------
// grid (75, 64), block 256. Two back-to-back smem GEMMs per s.
__global__ void __launch_bounds__(256, 2) y_kernel(
    const float* __restrict__ x, const float* __restrict__ wd,
    const float* __restrict__ bd)
{
    extern __shared__ float sm[];
    float* xS   = sm;                 // 6400: [ (c*4+tl)*25 + v ]  (linear copy of x tile)
    float* tmpS = xS + 6400;          // 64*116: [c][tl*28 + w], w padded to 28
    float* wdT  = tmpS + 64 * 116;    // 64*68: [c][o]
    float* adS  = wdT + 64 * 68;      // 3*700: [s][v*28 + w], pads zero
    float* bdS  = adS + 2100;         // 64
    float* bnS  = bdS + 64;           // 128

    const int n = blockIdx.y;
    const int t0 = blockIdx.x * TB;   // 75*4 = 300 exact, no partial t
    const int tid = threadIdx.x;
    const int pg = tid >> 3, wg = tid & 7;     // tmp-GEMM map: 8 pairs x 4 w
    const int tyo = tid >> 5, txc = tid & 31;  // GEMM map: 8 o x 4 cols (warp-uniform tyo)

    if (tid < 64) bdS[tid] = bd[tid] + bd[64 + tid] + bd[128 + tid];
    if (tid >= 64 && tid < 192) bnS[tid - 64] = 0.f;
    for (int i = tid; i < 2100; i += 256) {
        int si = i / 700, r = i - si * 700;
        int v = r / 28, w = r - v * 28;
        adS[i] = (w < 25) ? g_adapt[(size_t)n * 1875 + si * 625 + v * 25 + w] : 0.f;
    }
    // stage x tile: 64c x 4t x 25v contiguous per c -> 1600 float4 linear copy
    {
        float4* xS4 = reinterpret_cast<float4*>(xS);
        for (int i = tid; i < 1600; i += 256) {
            int c = i / 25, r = i - c * 25;
            const float4* xg = reinterpret_cast<const float4*>(
                x + ((size_t)n * Cc + c) * TV + t0 * 25);
            xS4[i] = xg[r];
        }
    }
    __syncthreads();

    float acc[8][4];
#pragma unroll
    for (int a = 0; a < 8; a++)
#pragma unroll
        for (int b = 0; b < 4; b++) acc[a][b] = 0.f;

    for (int s = 0; s < 3; s++) {
        // load wd[s] transposed (region independent of tmp-GEMM writes)
        for (int i = tid; i < 4096; i += 256) {
            int o = i >> 6, c = i & 63;
            wdT[c * 68 + o] = wd[s * 4096 + i];
        }
        // ---- tmp-GEMM: tmp[p, w] = sum_v xS[p, v] * adapt[v, w], p = c*4+tl ----
        if (wg < 7) {
            const float* ad = adS + s * 700;
            const int pbase = pg * 8;
            float a8[8][4];
#pragma unroll
            for (int k = 0; k < 8; k++)
#pragma unroll
                for (int j = 0; j < 4; j++) a8[k][j] = 0.f;
            for (int v = 0; v < 25; v++) {
                float4 a4 = *reinterpret_cast<const float4*>(ad + v * 28 + wg * 4);
#pragma unroll
                for (int k = 0; k < 8; k++) {
                    float xp = xS[(pbase + k) * 25 + v];
                    a8[k][0] += xp * a4.x;
                    a8[k][1] += xp * a4.y;
                    a8[k][2] += xp * a4.z;
                    a8[k][3] += xp * a4.w;
                }
            }
#pragma unroll
            for (int k = 0; k < 8; k++) {
                int p = pbase + k, c = p >> 2, tl = p & 3;
                *reinterpret_cast<float4*>(tmpS + c * 116 + tl * 28 + wg * 4) =
                    make_float4(a8[k][0], a8[k][1], a8[k][2], a8[k][3]);
            }
        }
        __syncthreads();

        // ---- GEMM: acc[o, col] += sum_c wdT[c][o] * tmpS[c][col] ----
        if (txc < 28) {
            for (int c = 0; c < 64; c++) {
                float4 w0 = *reinterpret_cast<const float4*>(wdT + c * 68 + tyo * 8);
                float4 w1 = *reinterpret_cast<const float4*>(wdT + c * 68 + tyo * 8 + 4);
                float4 t4 = *reinterpret_cast<const float4*>(tmpS + c * 116 + txc * 4);
                float wo[8] = {w0.x, w0.y, w0.z, w0.w, w1.x, w1.y, w1.z, w1.w};
#pragma unroll
                for (int jo = 0; jo < 8; jo++) {
                    acc[jo][0] += wo[jo] * t4.x;
                    acc[jo][1] += wo[jo] * t4.y;
                    acc[jo][2] += wo[jo] * t4.z;
                    acc[jo][3] += wo[jo] * t4.w;
                }
            }
        }
        __syncthreads();   // protect wdT/tmpS before next s
    }

    // ---- epilogue: bias, store y, BN partials ----
    if (txc < 28) {
        int tl = txc / 7;               // float4 group lies within one t
        int w0 = (txc % 7) * 4;
        int gt = t0 + tl;
#pragma unroll
        for (int jo = 0; jo < 8; jo++) {
            int o = tyo * 8 + jo;
            size_t base = ((size_t)n * Cc + o) * TV + gt * 25 + w0;
            float bias = bdS[o];
            float s1 = 0.f, s2 = 0.f;
#pragma unroll
            for (int j = 0; j < 4; j++) {
                if (w0 + j < 25) {
                    float val = acc[jo][j] + bias;
                    g_y[base + j] = val;
                    s1 += val;
                    s2 += val * val;
                }
            }
            atomicAdd(&bnS[o], s1);
            atomicAdd(&bnS[64 + o], s2);
        }
    }
    __syncthreads();
    if (tid < 128) atomicAdd(&g_bn[tid], bnS[tid]);
}

// -------- kernel 4: finalize BN stats --------
__global__ void bnfinal_kernel(const float* __restrict__ gamma,
                               const float* __restrict__ beta)
{
    int o = threadIdx.x;
    if (o < 64) {
        const float cnt = (float)Nn * (float)TV;
        float mean = g_bn[o] / cnt;
        float var = g_bn[64 + o] / cnt - mean * mean;
        float sc = gamma[o] * rsqrtf(var + 1e-5f);
        g_bn[128 + o] = sc;
        g_bn[192 + o] = beta[o] - mean * sc;
    }
}

// -------- kernel 5: out = relu(bn(y) + x), float4 --------
__global__ void final_kernel(const float* __restrict__ x, float* __restrict__ out)
{
    unsigned idx = blockIdx.x * 256u + threadIdx.x;       // < 7,680,000
    unsigned row = idx / 1875u;
    int c = (int)(row & 63u);
    size_t base = (size_t)idx * 4;
    float sc = g_bn[128 + c], sh = g_bn[192 + c];
    float4 y = *reinterpret_cast<const float4*>(g_y + base);
    float4 xr = *reinterpret_cast<const float4*>(x + base);
    float4 o;
    o.x = fmaxf(y.x * sc + sh + xr.x, 0.f);
    o.y = fmaxf(y.y * sc + sh + xr.y, 0.f);
    o.z = fmaxf(y.z * sc + sh + xr.z, 0.f);
    o.w = fmaxf(y.w * sc + sh + xr.w, 0.f);
    *reinterpret_cast<float4*>(out + base) = o;
}

extern "C" void kernel_launch(void* const* d_in, const int* in_sizes, int n_in,
                              void* d_out, int out_size)
{
    const float* x     = (const float*)d_in[0];
    const float* A     = (const float*)d_in[1];
    const float* W     = (const float*)d_in[2];
    const float* wa    = (const float*)d_in[3];
    const float* ba    = (const float*)d_in[4];
    const float* wb    = (const float*)d_in[5];
    const float* bb    = (const float*)d_in[6];
    const float* wd    = (const float*)d_in[7];
    const float* bd    = (const float*)d_in[8];
    const float* gamma = (const float*)d_in[9];
    const float* beta  = (const float*)d_in[10];
    float* out = (float*)d_out;

    const int PROJ_SMEM = (96 * 65 + 64 * 128 + 96) * 4;                            // 58112 B
    const int Y_SMEM    = (6400 + 64 * 116 + 64 * 68 + 2100 + 64 + 128) * 4;        // 81872 B
    cudaFuncSetAttribute(proj_kernel, cudaFuncAttributeMaxDynamicSharedMemorySize, PROJ_SMEM);
    cudaFuncSetAttribute(y_kernel,    cudaFuncAttributeMaxDynamicSharedMemorySize, Y_SMEM);

    zero_kernel<<<469, 256>>>();
    proj_kernel<<<dim3(59, 64), 256, PROJ_SMEM>>>(x, wa, ba, wb, bb);
    scores_part_kernel<<<dim3(3, 64, 4), 256>>>();
    softmax_adapt_kernel<<<192, 32>>>(A, W);
    y_kernel<<<dim3(75, 64), 256, Y_SMEM>>>(x, wd, bd);
    bnfinal_kernel<<<1, 64>>>(gamma, beta);
    final_kernel<<<30000, 256>>>(x, out);
}

// round 7
// speedup vs baseline: 1.3412x; 1.3412x over previous
#include <cuda_runtime.h>
#include <cstdint>

#define Nn 64
#define Cc 64
#define Tt 300
#define Vv 25
#define Ssub 3
#define TV 7500
#define TB 4

// -------- scratch (device globals: no allocation allowed) --------
__device__ float g_ab[(size_t)Nn * 96 * TV];      // [n][96 rows: 0-47 = a, 48-95 = b][t*25+v]
__device__ float g_adapt[Nn * Ssub * 625];        // [n][s][v][w]
__device__ float g_y[(size_t)Nn * Cc * TV];       // [n][o][t*25+w]
__device__ float g_bn[256];                       // sum | sumsq | scale | shift

// -------- tf32 helpers --------
__device__ __forceinline__ unsigned f2tf(float f) {
    unsigned r;
    asm("cvt.rna.tf32.f32 %0, %1;" : "=r"(r) : "f"(f));
    return r;
}
__device__ __forceinline__ void mma_tf32(float* d,
    unsigned a0, unsigned a1, unsigned a2, unsigned a3,
    unsigned b0, unsigned b1)
{
    asm volatile(
      "mma.sync.aligned.m16n8k8.row.col.f32.tf32.tf32.f32 "
      "{%0,%1,%2,%3}, {%4,%5,%6,%7}, {%8,%9}, {%0,%1,%2,%3};\n"
      : "+f"(d[0]), "+f"(d[1]), "+f"(d[2]), "+f"(d[3])
      : "r"(a0), "r"(a1), "r"(a2), "r"(a3), "r"(b0), "r"(b1));
}

// -------- kernel 0: zero BN accumulators --------
__global__ void zero_bn_kernel() {
    if (threadIdx.x < 128) g_bn[threadIdx.x] = 0.f;
}

// -------- kernel 1: AB[n] = [wa;wb][96,64] x x[n][64,7500]  (+bias) --------
__global__ void __launch_bounds__(256) proj_kernel(
    const float* __restrict__ x,
    const float* __restrict__ wa, const float* __restrict__ ba,
    const float* __restrict__ wb, const float* __restrict__ bb)
{
    extern __shared__ float sm[];
    float* Ws   = sm;               // 96*65
    float* Bs   = Ws + 96 * 65;     // 64*128
    float* biasS = Bs + 64 * 128;   // 96

    const int n = blockIdx.y;
    const int col0 = blockIdx.x * 128;
    const int tid = threadIdx.x;

    for (int i = tid; i < 96 * 64; i += 256) {
        int r = i >> 6, c = i & 63;
        Ws[r * 65 + c] = (r < 48) ? wa[r * 64 + c] : wb[(r - 48) * 64 + c];
    }
    if (tid < 96) biasS[tid] = (tid < 48) ? ba[tid] : bb[tid - 48];
    for (int i = tid; i < 64 * 128; i += 256) {
        int c = i >> 7, j = i & 127;
        int col = col0 + j;
        Bs[i] = (col < TV) ? x[((size_t)n * Cc + c) * TV + col] : 0.f;
    }
    __syncthreads();

    const int ty = tid >> 4, tx = tid & 15;
    float acc[6][8];
#pragma unroll
    for (int a = 0; a < 6; a++)
#pragma unroll
        for (int b = 0; b < 8; b++) acc[a][b] = 0.f;

    for (int c = 0; c < 64; c++) {
        float wr[6], xr[8];
#pragma unroll
        for (int jm = 0; jm < 6; jm++) wr[jm] = Ws[(ty * 6 + jm) * 65 + c];
#pragma unroll
        for (int jc = 0; jc < 8; jc++) xr[jc] = Bs[c * 128 + tx + 16 * jc];
#pragma unroll
        for (int jm = 0; jm < 6; jm++)
#pragma unroll
            for (int jc = 0; jc < 8; jc++) acc[jm][jc] += wr[jm] * xr[jc];
    }

#pragma unroll
    for (int jm = 0; jm < 6; jm++) {
        int r = ty * 6 + jm;
        size_t base = ((size_t)n * 96 + r) * TV;
        float bias = biasS[r];
#pragma unroll
        for (int jc = 0; jc < 8; jc++) {
            int col = col0 + tx + 16 * jc;
            if (col < TV) g_ab[base + col] = acc[jm][jc] + bias;
        }
    }
}

// -------- kernel 2: scores (K=4800) + softmax(axis=v) + adapt = A+W+attn --------
__global__ void __launch_bounds__(256) scores_kernel(
    const float* __restrict__ A, const float* __restrict__ W)
{
    __shared__ float aS[1000];
    __shared__ float bS[1000];
    __shared__ float scS[625];

    const int s = blockIdx.x, n = blockIdx.y;
    const int tid = threadIdx.x;

    for (int i = tid; i < 625; i += 256) scS[i] = 0.f;

    const size_t abase = ((size_t)n * 96 + s * 16) * TV;
    const size_t bbase = ((size_t)n * 96 + 48 + s * 16) * TV;

    const int ks = tid / 25;
    const int rem = tid % 25;
    const int wg = rem / 5, vg = rem % 5;

    float acc[5][5];
#pragma unroll
    for (int a = 0; a < 5; a++)
#pragma unroll
        for (int b = 0; b < 5; b++) acc[a][b] = 0.f;

    float4* aS4 = reinterpret_cast<float4*>(aS);
    float4* bS4 = reinterpret_cast<float4*>(bS);

    for (int st = 0; st < 120; st++) {
        __syncthreads();
        if (tid < 250) {
            const float4* ga = reinterpret_cast<const float4*>(g_ab + abase + (size_t)st * 1000);
            const float4* gb = reinterpret_cast<const float4*>(g_ab + bbase + (size_t)st * 1000);
            aS4[tid] = ga[tid];
            bS4[tid] = gb[tid];
        }
        __syncthreads();
        if (ks < 10) {
#pragma unroll
            for (int j = 0; j < 4; j++) {
                int k = ks * 4 + j;
                float ra[5], rb[5];
#pragma unroll
                for (int iv = 0; iv < 5; iv++) ra[iv] = aS[k * 25 + vg * 5 + iv];
#pragma unroll
                for (int iw = 0; iw < 5; iw++) rb[iw] = bS[k * 25 + wg * 5 + iw];
#pragma unroll
                for (int iv = 0; iv < 5; iv++)
#pragma unroll
                    for (int iw = 0; iw < 5; iw++) acc[iv][iw] += ra[iv] * rb[iw];
            }
        }
    }
    __syncthreads();
    if (ks < 10) {
#pragma unroll
        for (int iv = 0; iv < 5; iv++)
#pragma unroll
            for (int iw = 0; iw < 5; iw++)
                atomicAdd(&scS[(vg * 5 + iv) * 25 + (wg * 5 + iw)], acc[iv][iw]);
    }
    __syncthreads();

    if (tid < 25) {
        const int w = tid;
        const float inv = 1.f / 4800.f;
        float m = -1e30f;
        for (int v = 0; v < 25; v++) m = fmaxf(m, scS[v * 25 + w]);
        m *= inv;
        float sum = 0.f;
        for (int v = 0; v < 25; v++) {
            float ev = expf(scS[v * 25 + w] * inv - m);
            scS[v * 25 + w] = ev;
            sum += ev;
        }
        float rs = 1.f / sum;
        for (int v = 0; v < 25; v++) {
            int widx = (s * 25 + v) * 25 + w;
            g_adapt[((size_t)(n * 3 + s)) * 625 + v * 25 + w] =
                A[widx] + W[widx] + scS[v * 25 + w] * rs;
        }
    }
}

// -------- kernel 3: y = sum_s wd[s]^T (x . adapt[s]) + bd; GEMM on tensor cores --------
// grid (75, 64), block 256. TB=4 t per block -> 100 cols, 1 (c,t) pair per thread.
__global__ void __launch_bounds__(256, 3) y_kernel(
    const float* __restrict__ x, const float* __restrict__ wd,
    const float* __restrict__ bd)
{
    extern __shared__ float sm[];
    float* tmpS = sm;                 // 64*105: [c][tl*25+w], pads 100..104
    float* wdT  = tmpS + 64 * 105;    // 64*69:  [c][o]
    float* adS  = wdT + 64 * 69;      // 3*700:  [s][v*28+w], pads zero
    float* bdS  = adS + 2100;         // 64
    float* bnS  = bdS + 64;           // 128

    const int n = blockIdx.y;
    const int t0 = blockIdx.x * TB;
    const int tid = threadIdx.x;
    const int warp = tid >> 5, lane = tid & 31;
    const int g = lane >> 2, t = lane & 3;
    const int cc = tid & 63, tl = tid >> 6;   // this thread's (c, t-local) pair

    if (tid < 64) bdS[tid] = bd[tid] + bd[64 + tid] + bd[128 + tid];
    if (tid >= 64 && tid < 192) bnS[tid - 64] = 0.f;
    for (int i = tid; i < 2100; i += 256) {
        int si = i / 700, r = i - si * 700;
        int v = r / 28, w = r - v * 28;
        adS[i] = (w < 25) ? g_adapt[(size_t)n * 1875 + si * 625 + v * 25 + w] : 0.f;
    }
    // stage x tile (64 x 100) into tmpS rows (stride 105)
    for (int i4 = tid; i4 < 1600; i4 += 256) {
        int c = i4 / 25, r4 = i4 - c * 25;
        float4 xw = *reinterpret_cast<const float4*>(
            x + ((size_t)n * Cc + c) * TV + t0 * 25 + r4 * 4);
        float* dst = tmpS + c * 105 + r4 * 4;
        dst[0] = xw.x; dst[1] = xw.y; dst[2] = xw.z; dst[3] = xw.w;
    }
    __syncthreads();

    // cache this thread's x row in registers
    float xv[25];
#pragma unroll
    for (int v = 0; v < 25; v++) xv[v] = tmpS[cc * 105 + tl * 25 + v];
    __syncthreads();

    float acc[4][2][4];
#pragma unroll
    for (int a = 0; a < 4; a++)
#pragma unroll
        for (int b = 0; b < 2; b++)
#pragma unroll
            for (int c = 0; c < 4; c++) acc[a][b][c] = 0.f;

    const int ntc = (warp < 6) ? 2 : (warp == 6 ? 1 : 0);

    for (int s = 0; s < 3; s++) {
        // load wd[s] transposed: wdT[c][o]
        for (int i = tid; i < 4096; i += 256) {
            int o = i >> 6, c = i & 63;
            wdT[c * 69 + o] = wd[s * 4096 + i];
        }
        const float* ad = adS + s * 700;
        // ---- tmp: tmpS[cc][tl*25+w] = sum_v xv[v]*adapt[v][w], 3 w-passes ----
        {
            float a8[8];
#pragma unroll
            for (int i = 0; i < 8; i++) a8[i] = 0.f;
            for (int v = 0; v < 25; v++) {
                float xr = xv[v];
#pragma unroll
                for (int w4 = 0; w4 < 2; w4++) {
                    float4 t4 = *reinterpret_cast<const float4*>(ad + v * 28 + w4 * 4);
                    a8[w4 * 4 + 0] += xr * t4.x;
                    a8[w4 * 4 + 1] += xr * t4.y;
                    a8[w4 * 4 + 2] += xr * t4.z;
                    a8[w4 * 4 + 3] += xr * t4.w;
                }
            }
#pragma unroll
            for (int w = 0; w < 8; w++) tmpS[cc * 105 + tl * 25 + w] = a8[w];
        }
        {
            float a8[8];
#pragma unroll
            for (int i = 0; i < 8; i++) a8[i] = 0.f;
            for (int v = 0; v < 25; v++) {
                float xr = xv[v];
#pragma unroll
                for (int w4 = 0; w4 < 2; w4++) {
                    float4 t4 = *reinterpret_cast<const float4*>(ad + v * 28 + 8 + w4 * 4);
                    a8[w4 * 4 + 0] += xr * t4.x;
                    a8[w4 * 4 + 1] += xr * t4.y;
                    a8[w4 * 4 + 2] += xr * t4.z;
                    a8[w4 * 4 + 3] += xr * t4.w;
                }
            }
#pragma unroll
            for (int w = 0; w < 8; w++) tmpS[cc * 105 + tl * 25 + 8 + w] = a8[w];
        }
        {
            float a12[12];
#pragma unroll
            for (int i = 0; i < 12; i++) a12[i] = 0.f;
            for (int v = 0; v < 25; v++) {
                float xr = xv[v];
#pragma unroll
                for (int w4 = 0; w4 < 3; w4++) {
                    float4 t4 = *reinterpret_cast<const float4*>(ad + v * 28 + 16 + w4 * 4);
                    a12[w4 * 4 + 0] += xr * t4.x;
                    a12[w4 * 4 + 1] += xr * t4.y;
                    a12[w4 * 4 + 2] += xr * t4.z;
                    a12[w4 * 4 + 3] += xr * t4.w;
                }
            }
#pragma unroll
            for (int w = 0; w < 9; w++) tmpS[cc * 105 + tl * 25 + 16 + w] = a12[w];
        }
        __syncthreads();

        // ---- mma GEMM: D[64o x 100col] += wd[s][o][c] * tmpS[c][col], 3xTF32 ----
        if (ntc > 0) {
            for (int k0 = 0; k0 < 64; k0 += 8) {
                unsigned bh[2][2], bl[2][2];
#pragma unroll
                for (int nt = 0; nt < 2; nt++) {
                    if (nt < ntc) {
                        int colb = warp * 16 + nt * 8 + g;
                        float b0 = tmpS[(k0 + t) * 105 + colb];
                        float b1 = tmpS[(k0 + t + 4) * 105 + colb];
                        bh[nt][0] = f2tf(b0);
                        bl[nt][0] = f2tf(b0 - __uint_as_float(bh[nt][0]));
                        bh[nt][1] = f2tf(b1);
                        bl[nt][1] = f2tf(b1 - __uint_as_float(bh[nt][1]));
                    }
                }
#pragma unroll
                for (int ot = 0; ot < 4; ot++) {
                    float a0 = wdT[(k0 + t) * 69 + ot * 16 + g];
                    float a1 = wdT[(k0 + t) * 69 + ot * 16 + g + 8];
                    float a2 = wdT[(k0 + t + 4) * 69 + ot * 16 + g];
                    float a3 = wdT[(k0 + t + 4) * 69 + ot * 16 + g + 8];
                    unsigned ah0 = f2tf(a0), ah1 = f2tf(a1), ah2 = f2tf(a2), ah3 = f2tf(a3);
                    unsigned al0 = f2tf(a0 - __uint_as_float(ah0));
                    unsigned al1 = f2tf(a1 - __uint_as_float(ah1));
                    unsigned al2 = f2tf(a2 - __uint_as_float(ah2));
                    unsigned al3 = f2tf(a3 - __uint_as_float(ah3));
                    for (int nt = 0; nt < ntc; nt++) {
                        mma_tf32(acc[ot][nt], ah0, ah1, ah2, ah3, bh[nt][0], bh[nt][1]);
                        mma_tf32(acc[ot][nt], al0, al1, al2, al3, bh[nt][0], bh[nt][1]);
                        mma_tf32(acc[ot][nt], ah0, ah1, ah2, ah3, bl[nt][0], bl[nt][1]);
                    }
                }
            }
        }
        __syncthreads();
    }

    // ---- epilogue: bias, store y, BN partials ----
    if (ntc > 0) {
        const int col_base = warp * 16 + 2 * t;
#pragma unroll
        for (int ot = 0; ot < 4; ot++) {
#pragma unroll
            for (int h = 0; h < 2; h++) {
                int o = ot * 16 + g + 8 * h;
                float bias = bdS[o];
                size_t rb = ((size_t)n * Cc + o) * TV + t0 * 25;
                float s1 = 0.f, s2 = 0.f;
                for (int nt = 0; nt < ntc; nt++) {
#pragma unroll
                    for (int j = 0; j < 2; j++) {
                        int col = col_base + nt * 8 + j;
                        if (col < 100) {
                            float val = acc[ot][nt][2 * h + j] + bias;
                            g_y[rb + col] = val;
                            s1 += val;
                            s2 += val * val;
                        }
                    }
                }
                atomicAdd(&bnS[o], s1);
                atomicAdd(&bnS[64 + o], s2);
            }
        }
    }
    __syncthreads();
    if (tid < 128) atomicAdd(&g_bn[tid], bnS[tid]);
}

// -------- kernel 4: finalize BN stats --------
__global__ void bnfinal_kernel(const float* __restrict__ gamma,
                               const float* __restrict__ beta)
{
    int o = threadIdx.x;
    if (o < 64) {
        const float cnt = (float)Nn * (float)TV;
        float mean = g_bn[o] / cnt;
        float var = g_bn[64 + o] / cnt - mean * mean;
        float sc = gamma[o] * rsqrtf(var + 1e-5f);
        g_bn[128 + o] = sc;
        g_bn[192 + o] = beta[o] - mean * sc;
    }
}

// -------- kernel 5: out = relu(bn(y) + x), float4 --------
__global__ void final_kernel(const float* __restrict__ x, float* __restrict__ out)
{
    unsigned idx = blockIdx.x * 256u + threadIdx.x;       // < 7,680,000
    unsigned row = idx / 1875u;
    int c = (int)(row & 63u);
    size_t base = (size_t)idx * 4;
    float sc = g_bn[128 + c], sh = g_bn[192 + c];
    float4 y = *reinterpret_cast<const float4*>(g_y + base);
    float4 xr = *reinterpret_cast<const float4*>(x + base);
    float4 o;
    o.x = fmaxf(y.x * sc + sh + xr.x, 0.f);
    o.y = fmaxf(y.y * sc + sh + xr.y, 0.f);
    o.z = fmaxf(y.z * sc + sh + xr.z, 0.f);
    o.w = fmaxf(y.w * sc + sh + xr.w, 0.f);
    *reinterpret_cast<float4*>(out + base) = o;
}

extern "C" void kernel_launch(void* const* d_in, const int* in_sizes, int n_in,
                              void* d_out, int out_size)
{
    const float* x     = (const float*)d_in[0];
    const float* A     = (const float*)d_in[1];
    const float* W     = (const float*)d_in[2];
    const float* wa    = (const float*)d_in[3];
    const float* ba    = (const float*)d_in[4];
    const float* wb    = (const float*)d_in[5];
    const float* bb    = (const float*)d_in[6];
    const float* wd    = (const float*)d_in[7];
    const float* bd    = (const float*)d_in[8];
    const float* gamma = (const float*)d_in[9];
    const float* beta  = (const float*)d_in[10];
    float* out = (float*)d_out;

    const int PROJ_SMEM = (96 * 65 + 64 * 128 + 96) * 4;                       // 58112 B
    const int Y_SMEM    = (64 * 105 + 64 * 69 + 2100 + 64 + 128) * 4;          // 53712 B
    cudaFuncSetAttribute(proj_kernel, cudaFuncAttributeMaxDynamicSharedMemorySize, PROJ_SMEM);
    cudaFuncSetAttribute(y_kernel,    cudaFuncAttributeMaxDynamicSharedMemorySize, Y_SMEM);

    zero_bn_kernel<<<1, 128>>>();
    proj_kernel<<<dim3(59, 64), 256, PROJ_SMEM>>>(x, wa, ba, wb, bb);
    scores_kernel<<<dim3(3, 64), 256>>>(A, W);
    y_kernel<<<dim3(75, 64), 256, Y_SMEM>>>(x, wd, bd);
    bnfinal_kernel<<<1, 64>>>(gamma, beta);
    final_kernel<<<30000, 256>>>(x, out);
}

// round 9
// speedup vs baseline: 1.6367x; 1.2203x over previous
#include <cuda_runtime.h>
#include <cstdint>

#define Nn 64
#define Cc 64
#define Tt 300
#define Vv 25
#define Ssub 3
#define TV 7500
#define TB 4

// -------- scratch (device globals: no allocation allowed) --------
__device__ float g_ab[(size_t)Nn * 96 * TV];      // [n][96 rows: 0-47 = a, 48-95 = b][t*25+v]
__device__ float g_adapt[Nn * Ssub * 625];        // [n][s][v][w]
__device__ float g_y[(size_t)Nn * Cc * TV];       // [n][o][t*25+w]
__device__ float g_bn[256];                       // sum | sumsq | scale | shift

// -------- tf32 helpers --------
__device__ __forceinline__ unsigned f2tf(float f) {
    unsigned r;
    asm("cvt.rna.tf32.f32 %0, %1;" : "=r"(r) : "f"(f));
    return r;
}
__device__ __forceinline__ void mma_tf32(float* d,
    unsigned a0, unsigned a1, unsigned a2, unsigned a3,
    unsigned b0, unsigned b1)
{
    asm volatile(
      "mma.sync.aligned.m16n8k8.row.col.f32.tf32.tf32.f32 "
      "{%0,%1,%2,%3}, {%4,%5,%6,%7}, {%8,%9}, {%0,%1,%2,%3};\n"
      : "+f"(d[0]), "+f"(d[1]), "+f"(d[2]), "+f"(d[3])
      : "r"(a0), "r"(a1), "r"(a2), "r"(a3), "r"(b0), "r"(b1));
}

// -------- kernel 0: zero BN accumulators --------
__global__ void zero_bn_kernel() {
    if (threadIdx.x < 128) g_bn[threadIdx.x] = 0.f;
}

// -------- kernel 1: AB[n] = [wa;wb][96,64] x x[n][64,7500]  (+bias) --------
__global__ void __launch_bounds__(256) proj_kernel(
    const float* __restrict__ x,
    const float* __restrict__ wa, const float* __restrict__ ba,
    const float* __restrict__ wb, const float* __restrict__ bb)
{
    extern __shared__ float sm[];
    float* Ws   = sm;               // 96*65
    float* Bs   = Ws + 96 * 65;     // 64*128
    float* biasS = Bs + 64 * 128;   // 96

    const int n = blockIdx.y;
    const int col0 = blockIdx.x * 128;
    const int tid = threadIdx.x;

    for (int i = tid; i < 96 * 64; i += 256) {
        int r = i >> 6, c = i & 63;
        Ws[r * 65 + c] = (r < 48) ? wa[r * 64 + c] : wb[(r - 48) * 64 + c];
    }
    if (tid < 96) biasS[tid] = (tid < 48) ? ba[tid] : bb[tid - 48];
    for (int i = tid; i < 64 * 128; i += 256) {
        int c = i >> 7, j = i & 127;
        int col = col0 + j;
        Bs[i] = (col < TV) ? x[((size_t)n * Cc + c) * TV + col] : 0.f;
    }
    __syncthreads();

    const int ty = tid >> 4, tx = tid & 15;
    float acc[6][8];
#pragma unroll
    for (int a = 0; a < 6; a++)
#pragma unroll
        for (int b = 0; b < 8; b++) acc[a][b] = 0.f;

    for (int c = 0; c < 64; c++) {
        float wr[6], xr[8];
#pragma unroll
        for (int jm = 0; jm < 6; jm++) wr[jm] = Ws[(ty * 6 + jm) * 65 + c];
#pragma unroll
        for (int jc = 0; jc < 8; jc++) xr[jc] = Bs[c * 128 + tx + 16 * jc];
#pragma unroll
        for (int jm = 0; jm < 6; jm++)
#pragma unroll
            for (int jc = 0; jc < 8; jc++) acc[jm][jc] += wr[jm] * xr[jc];
    }

#pragma unroll
    for (int jm = 0; jm < 6; jm++) {
        int r = ty * 6 + jm;
        size_t base = ((size_t)n * 96 + r) * TV;
        float bias = biasS[r];
#pragma unroll
        for (int jc = 0; jc < 8; jc++) {
            int col = col0 + tx + 16 * jc;
            if (col < TV) g_ab[base + col] = acc[jm][jc] + bias;
        }
    }
}

// -------- kernel 2: scores (K=4800) + softmax(axis=v) + adapt = A+W+attn --------
__global__ void __launch_bounds__(256) scores_kernel(
    const float* __restrict__ A, const float* __restrict__ W)
{
    __shared__ float aS[1000];
    __shared__ float bS[1000];
    __shared__ float scS[625];

    const int s = blockIdx.x, n = blockIdx.y;
    const int tid = threadIdx.x;

    for (int i = tid; i < 625; i += 256) scS[i] = 0.f;

    const size_t abase = ((size_t)n * 96 + s * 16) * TV;
    const size_t bbase = ((size_t)n * 96 + 48 + s * 16) * TV;

    const int ks = tid / 25;
    const int rem = tid % 25;
    const int wg = rem / 5, vg = rem % 5;

    float acc[5][5];
#pragma unroll
    for (int a = 0; a < 5; a++)
#pragma unroll
        for (int b = 0; b < 5; b++) acc[a][b] = 0.f;

    float4* aS4 = reinterpret_cast<float4*>(aS);
    float4* bS4 = reinterpret_cast<float4*>(bS);

    for (int st = 0; st < 120; st++) {
        __syncthreads();
        if (tid < 250) {
            const float4* ga = reinterpret_cast<const float4*>(g_ab + abase + (size_t)st * 1000);
            const float4* gb = reinterpret_cast<const float4*>(g_ab + bbase + (size_t)st * 1000);
            aS4[tid] = ga[tid];
            bS4[tid] = gb[tid];
        }
        __syncthreads();
        if (ks < 10) {
#pragma unroll
            for (int j = 0; j < 4; j++) {
                int k = ks * 4 + j;
                float ra[5], rb[5];
#pragma unroll
                for (int iv = 0; iv < 5; iv++) ra[iv] = aS[k * 25 + vg * 5 + iv];
#pragma unroll
                for (int iw = 0; iw < 5; iw++) rb[iw] = bS[k * 25 + wg * 5 + iw];
#pragma unroll
                for (int iv = 0; iv < 5; iv++)
#pragma unroll
                    for (int iw = 0; iw < 5; iw++) acc[iv][iw] += ra[iv] * rb[iw];
            }
        }
    }
    __syncthreads();
    if (ks < 10) {
#pragma unroll
        for (int iv = 0; iv < 5; iv++)
#pragma unroll
            for (int iw = 0; iw < 5; iw++)
                atomicAdd(&scS[(vg * 5 + iv) * 25 + (wg * 5 + iw)], acc[iv][iw]);
    }
    __syncthreads();

    if (tid < 25) {
        const int w = tid;
        const float inv = 1.f / 4800.f;
        float m = -1e30f;
        for (int v = 0; v < 25; v++) m = fmaxf(m, scS[v * 25 + w]);
        m *= inv;
        float sum = 0.f;
        for (int v = 0; v < 25; v++) {
            float ev = expf(scS[v * 25 + w] * inv - m);
            scS[v * 25 + w] = ev;
            sum += ev;
        }
        float rs = 1.f / sum;
        for (int v = 0; v < 25; v++) {
            int widx = (s * 25 + v) * 25 + w;
            g_adapt[((size_t)(n * 3 + s)) * 625 + v * 25 + w] =
                A[widx] + W[widx] + scS[v * 25 + w] * rs;
        }
    }
}

// -------- kernel 3: y = sum_s wd[s]^T (x . adapt[s]) + bd; plain TF32 MMA --------
// grid (75, 64), block 256. All tf32 conversions hoisted out of the GEMM loop:
// wdT and tmpS hold PRE-ROUNDED tf32 bit patterns (stored as floats).
__global__ void __launch_bounds__(256, 3) y_kernel(
    const float* __restrict__ x, const float* __restrict__ wd,
    const float* __restrict__ bd)
{
    extern __shared__ float sm[];
    float* tmpS = sm;                 // 64*105: [c][tl*25+w] (tf32-rounded), pads 100..104 = 0
    float* wdT  = tmpS + 64 * 105;    // 64*69:  [c][o] (tf32-rounded)
    float* adS  = wdT + 64 * 69;      // 3*700:  [s][v*28+w], pads zero
    float* bdS  = adS + 2100;         // 64
    float* bnS  = bdS + 64;           // 128

    const int n = blockIdx.y;
    const int t0 = blockIdx.x * TB;
    const int tid = threadIdx.x;
    const int warp = tid >> 5, lane = tid & 31;
    const int g = lane >> 2, t = lane & 3;
    const int cc = tid & 63, tl = tid >> 6;   // this thread's (c, t-local) pair

    if (tid < 64) bdS[tid] = bd[tid] + bd[64 + tid] + bd[128 + tid];
    if (tid >= 64 && tid < 192) bnS[tid - 64] = 0.f;
    for (int i = tid; i < 2100; i += 256) {
        int si = i / 700, r = i - si * 700;
        int v = r / 28, w = r - v * 28;
        adS[i] = (w < 25) ? g_adapt[(size_t)n * 1875 + si * 625 + v * 25 + w] : 0.f;
    }
    // stage x tile (64 x 100) into tmpS rows (stride 105); zero pad cols
    for (int i4 = tid; i4 < 1600; i4 += 256) {
        int c = i4 / 25, r4 = i4 - c * 25;
        float4 xw = *reinterpret_cast<const float4*>(
            x + ((size_t)n * Cc + c) * TV + t0 * 25 + r4 * 4);
        float* dst = tmpS + c * 105 + r4 * 4;
        dst[0] = xw.x; dst[1] = xw.y; dst[2] = xw.z; dst[3] = xw.w;
    }
    for (int i = tid; i < 320; i += 256) {
        int c = i / 5, p = i % 5;
        tmpS[c * 105 + 100 + p] = 0.f;
    }
    __syncthreads();

    // cache this thread's x row in registers
    float xv[25];
#pragma unroll
    for (int v = 0; v < 25; v++) xv[v] = tmpS[cc * 105 + tl * 25 + v];
    __syncthreads();

    float acc[4][2][4];
#pragma unroll
    for (int a = 0; a < 4; a++)
#pragma unroll
        for (int b = 0; b < 2; b++)
#pragma unroll
            for (int c = 0; c < 4; c++) acc[a][b][c] = 0.f;

    const int ntc = (warp < 6) ? 2 : (warp == 6 ? 1 : 0);

    for (int s = 0; s < 3; s++) {
        // load wd[s] transposed, pre-rounded to tf32: wdT[c][o]
        for (int i = tid; i < 4096; i += 256) {
            int o = i >> 6, c = i & 63;
            wdT[c * 69 + o] = __uint_as_float(f2tf(wd[s * 4096 + i]));
        }
        const float* ad = adS + s * 700;
        // ---- tmp: tmpS[cc][tl*25+w] = tf32(sum_v xv[v]*adapt[v][w]), 3 w-passes ----
        {
            float a8[8];
#pragma unroll
            for (int i = 0; i < 8; i++) a8[i] = 0.f;
            for (int v = 0; v < 25; v++) {
                float xr = xv[v];
#pragma unroll
                for (int w4 = 0; w4 < 2; w4++) {
                    float4 t4 = *reinterpret_cast<const float4*>(ad + v * 28 + w4 * 4);
                    a8[w4 * 4 + 0] += xr * t4.x;
                    a8[w4 * 4 + 1] += xr * t4.y;
                    a8[w4 * 4 + 2] += xr * t4.z;
                    a8[w4 * 4 + 3] += xr * t4.w;
                }
            }
#pragma unroll
            for (int w = 0; w < 8; w++)
                tmpS[cc * 105 + tl * 25 + w] = __uint_as_float(f2tf(a8[w]));
        }
        {
            float a8[8];
#pragma unroll
            for (int i = 0; i < 8; i++) a8[i] = 0.f;
            for (int v = 0; v < 25; v++) {
                float xr = xv[v];
#pragma unroll
                for (int w4 = 0; w4 < 2; w4++) {
                    float4 t4 = *reinterpret_cast<const float4*>(ad + v * 28 + 8 + w4 * 4);
                    a8[w4 * 4 + 0] += xr * t4.x;
                    a8[w4 * 4 + 1] += xr * t4.y;
                    a8[w4 * 4 + 2] += xr * t4.z;
                    a8[w4 * 4 + 3] += xr * t4.w;
                }
            }
#pragma unroll
            for (int w = 0; w < 8; w++)
                tmpS[cc * 105 + tl * 25 + 8 + w] = __uint_as_float(f2tf(a8[w]));
        }
        {
            float a12[12];
#pragma unroll
            for (int i = 0; i < 12; i++) a12[i] = 0.f;
            for (int v = 0; v < 25; v++) {
                float xr = xv[v];
#pragma unroll
                for (int w4 = 0; w4 < 3; w4++) {
                    float4 t4 = *reinterpret_cast<const float4*>(ad + v * 28 + 16 + w4 * 4);
                    a12[w4 * 4 + 0] += xr * t4.x;
                    a12[w4 * 4 + 1] += xr * t4.y;
                    a12[w4 * 4 + 2] += xr * t4.z;
                    a12[w4 * 4 + 3] += xr * t4.w;
                }
            }
#pragma unroll
            for (int w = 0; w < 9; w++)
                tmpS[cc * 105 + tl * 25 + 16 + w] = __uint_as_float(f2tf(a12[w]));
        }
        __syncthreads();

        // ---- mma GEMM: D[64o x 100col] += wd[s][o][c] * tmp[c][col], pure LDS+MMA ----
        if (ntc > 0) {
            for (int k0 = 0; k0 < 64; k0 += 8) {
                unsigned bf[2][2];
#pragma unroll
                for (int nt = 0; nt < 2; nt++) {
                    if (nt < ntc) {
                        int colb = warp * 16 + nt * 8 + g;
                        bf[nt][0] = __float_as_uint(tmpS[(k0 + t) * 105 + colb]);
                        bf[nt][1] = __float_as_uint(tmpS[(k0 + t + 4) * 105 + colb]);
                    }
                }
#pragma unroll
                for (int ot = 0; ot < 4; ot++) {
                    unsigned a0 = __float_as_uint(wdT[(k0 + t) * 69 + ot * 16 + g]);
                    unsigned a1 = __float_as_uint(wdT[(k0 + t) * 69 + ot * 16 + g + 8]);
                    unsigned a2 = __float_as_uint(wdT[(k0 + t + 4) * 69 + ot * 16 + g]);
                    unsigned a3 = __float_as_uint(wdT[(k0 + t + 4) * 69 + ot * 16 + g + 8]);
                    for (int nt = 0; nt < ntc; nt++)
                        mma_tf32(acc[ot][nt], a0, a1, a2, a3, bf[nt][0], bf[nt][1]);
                }
            }
        }
        __syncthreads();   // protect wdT/tmpS before next s
    }

    // ---- epilogue: bias, store y, BN partials ----
    if (ntc > 0) {
        const int col_base = warp * 16 + 2 * t;
#pragma unroll
        for (int ot = 0; ot < 4; ot++) {
#pragma unroll
            for (int h = 0; h < 2; h++) {
                int o = ot * 16 + g + 8 * h;
                float bias = bdS[o];
                size_t rb = ((size_t)n * Cc + o) * TV + t0 * 25;
                float s1 = 0.f, s2 = 0.f;
                for (int nt = 0; nt < ntc; nt++) {
#pragma unroll
                    for (int j = 0; j < 2; j++) {
                        int col = col_base + nt * 8 + j;
                        if (col < 100) {
                            float val = acc[ot][nt][2 * h + j] + bias;
                            g_y[rb + col] = val;
                            s1 += val;
                            s2 += val * val;
                        }
                    }
                }
                atomicAdd(&bnS[o], s1);
                atomicAdd(&bnS[64 + o], s2);
            }
        }
    }
    __syncthreads();
    if (tid < 128) atomicAdd(&g_bn[tid], bnS[tid]);
}

// -------- kernel 4: finalize BN stats --------
__global__ void bnfinal_kernel(const float* __restrict__ gamma,
                               const float* __restrict__ beta)
{
    int o = threadIdx.x;
    if (o < 64) {
        const float cnt = (float)Nn * (float)TV;
        float mean = g_bn[o] / cnt;
        float var = g_bn[64 + o] / cnt - mean * mean;
        float sc = gamma[o] * rsqrtf(var + 1e-5f);
        g_bn[128 + o] = sc;
        g_bn[192 + o] = beta[o] - mean * sc;
    }
}

// -------- kernel 5: out = relu(bn(y) + x), float4 --------
__global__ void final_kernel(const float* __restrict__ x, float* __restrict__ out)
{
    unsigned idx = blockIdx.x * 256u + threadIdx.x;       // < 7,680,000
    unsigned row = idx / 1875u;
    int c = (int)(row & 63u);
    size_t base = (size_t)idx * 4;
    float sc = g_bn[128 + c], sh = g_bn[192 + c];
    float4 y = *reinterpret_cast<const float4*>(g_y + base);
    float4 xr = *reinterpret_cast<const float4*>(x + base);
    float4 o;
    o.x = fmaxf(y.x * sc + sh + xr.x, 0.f);
    o.y = fmaxf(y.y * sc + sh + xr.y, 0.f);
    o.z = fmaxf(y.z * sc + sh + xr.z, 0.f);
    o.w = fmaxf(y.w * sc + sh + xr.w, 0.f);
    *reinterpret_cast<float4*>(out + base) = o;
}

extern "C" void kernel_launch(void* const* d_in, const int* in_sizes, int n_in,
                              void* d_out, int out_size)
{
    const float* x     = (const float*)d_in[0];
    const float* A     = (const float*)d_in[1];
    const float* W     = (const float*)d_in[2];
    const float* wa    = (const float*)d_in[3];
    const float* ba    = (const float*)d_in[4];
    const float* wb    = (const float*)d_in[5];
    const float* bb    = (const float*)d_in[6];
    const float* wd    = (const float*)d_in[7];
    const float* bd    = (const float*)d_in[8];
    const float* gamma = (const float*)d_in[9];
    const float* beta  = (const float*)d_in[10];
    float* out = (float*)d_out;

    const int PROJ_SMEM = (96 * 65 + 64 * 128 + 96) * 4;                       // 58112 B
    const int Y_SMEM    = (64 * 105 + 64 * 69 + 2100 + 64 + 128) * 4;          // 53712 B
    cudaFuncSetAttribute(proj_kernel, cudaFuncAttributeMaxDynamicSharedMemorySize, PROJ_SMEM);
    cudaFuncSetAttribute(y_kernel,    cudaFuncAttributeMaxDynamicSharedMemorySize, Y_SMEM);

    zero_bn_kernel<<<1, 128>>>();
    proj_kernel<<<dim3(59, 64), 256, PROJ_SMEM>>>(x, wa, ba, wb, bb);
    scores_kernel<<<dim3(3, 64), 256>>>(A, W);
    y_kernel<<<dim3(75, 64), 256, Y_SMEM>>>(x, wd, bd);
    bnfinal_kernel<<<1, 64>>>(gamma, beta);
    final_kernel<<<30000, 256>>>(x, out);
}